// round 1
// baseline (speedup 1.0000x reference)
#include <cuda_runtime.h>
#include <math.h>
#include <stdint.h>

#define HID  1024
#define FFN  4096
#define NE   8
#define NTOK 4096
#define CAP  9216   // 8192 pairs + 8*128 max padding

// ---------------- scratch (device globals; no allocation allowed) ----------------
__device__ int   g_cnt[NE];
__device__ int   g_off[NE + 1];   // 128-aligned padded segment starts
__device__ int   g_end[NE];       // off[e] + cnt[e]
__device__ int   g_cur[NE];
__device__ int   g_rowTok[CAP];
__device__ int   g_tok2[NTOK * 2];
__device__ float g_w2[NTOK * 2];
__device__ int   g_pairPos[NTOK * 2];
__device__ float g_H[(size_t)CAP * FFN];   // expert-hidden activations
__device__ float g_Y[(size_t)CAP * HID];   // per-pair expert outputs

__device__ __forceinline__ float to_tf32(float x) {
    unsigned u;
    asm("cvt.rna.tf32.f32 %0, %1;" : "=r"(u) : "f"(x));
    return __uint_as_float(u);
}

// ---------------- tiny setup kernels ----------------
__global__ void k_zero() {
    if (threadIdx.x < NE) g_cnt[threadIdx.x] = 0;
}

// one warp per token: logits = x @ Wr, top-2, pairwise softmax
__global__ void k_router(const float* __restrict__ x, const float* __restrict__ Wr) {
    int warp = threadIdx.x >> 5, lane = threadIdx.x & 31;
    int t = blockIdx.x * 8 + warp;
    const float* xr = x + (size_t)t * HID;
    float acc[NE];
#pragma unroll
    for (int e = 0; e < NE; e++) acc[e] = 0.f;
    for (int i = lane; i < HID; i += 32) {
        float xv = xr[i];
        const float4* w = (const float4*)(Wr + (size_t)i * NE);
        float4 w0 = w[0], w1 = w[1];
        acc[0] += xv * w0.x; acc[1] += xv * w0.y; acc[2] += xv * w0.z; acc[3] += xv * w0.w;
        acc[4] += xv * w1.x; acc[5] += xv * w1.y; acc[6] += xv * w1.z; acc[7] += xv * w1.w;
    }
#pragma unroll
    for (int e = 0; e < NE; e++)
#pragma unroll
        for (int s = 16; s > 0; s >>= 1) acc[e] += __shfl_xor_sync(0xffffffffu, acc[e], s);
    if (lane == 0) {
        int i0 = 0; float m0 = acc[0];
#pragma unroll
        for (int e = 1; e < NE; e++) if (acc[e] > m0) { m0 = acc[e]; i0 = e; }
        int i1 = -1; float m1 = -1e30f;
#pragma unroll
        for (int e = 0; e < NE; e++) if (e != i0 && acc[e] > m1) { m1 = acc[e]; i1 = e; }
        // softmax over full 8 then renormalize top-2 == pairwise softmax of top-2 logits
        float w0 = 1.f / (1.f + expf(m1 - m0));
        g_tok2[2 * t] = i0; g_tok2[2 * t + 1] = i1;
        g_w2[2 * t] = w0;   g_w2[2 * t + 1] = 1.f - w0;
        atomicAdd(&g_cnt[i0], 1);
        atomicAdd(&g_cnt[i1], 1);
    }
}

__global__ void k_offsets() {
    if (threadIdx.x == 0) {
        int o = 0;
#pragma unroll
        for (int e = 0; e < NE; e++) {
            g_off[e] = o; g_end[e] = o + g_cnt[e]; g_cur[e] = o;
            o += (g_cnt[e] + 127) & ~127;
        }
        g_off[NE] = o;
    }
}

__global__ void k_place() {
    int p = blockIdx.x * blockDim.x + threadIdx.x;
    if (p < NTOK * 2) {
        int e = g_tok2[p];
        int r = atomicAdd(&g_cur[e], 1);
        g_rowTok[r] = p >> 1;
        g_pairPos[p] = r;
    }
}

// ---------------- grouped GEMM: C[128x128] tiles, TF32 mma.sync ----------------
// BM=128 BN=128 BK=16; 8 warps, each 64x32 (4x4 m16n8k8 tiles, 2 k-steps)
template <int KD, int ND, bool DOGELU, bool INDIRECT>
__global__ void k_gemm(const float* __restrict__ Abase,
                       const float* __restrict__ Wall,
                       const float* __restrict__ Ball) {
    __shared__ float sA[128][18];    // row-major, +2 pad
    __shared__ float sB[16][136];    // row-major, +8 pad (conflict-free frag reads)

    int row0 = blockIdx.y * 128;
    if (row0 >= g_off[NE]) return;
    int e = 0;
    while (row0 >= g_off[e + 1]) e++;
    int rend = g_end[e];
    int nblk = blockIdx.x * 128;

    const float* Asrc = INDIRECT ? Abase : (const float*)g_H;
    float*       C    = DOGELU ? g_H : g_Y;

    const float* B    = Wall + (size_t)e * KD * ND + nblk;
    const float* bias = Ball + (size_t)e * ND + nblk;

    int tid = threadIdx.x;
    int am = tid >> 2;           // 0..63 (two passes over 128 rows)
    int ak = (tid & 3) * 4;      // k within tile (float4)
    int bn = (tid & 31) * 4;     // n within tile (float4)
    int bk = tid >> 5;           // 0..7 (two passes over 16 k-rows)

    const float* aptr[2];
#pragma unroll
    for (int p = 0; p < 2; p++) {
        int r = row0 + am + 64 * p;
        if (r < rend) {
            if (INDIRECT) aptr[p] = Asrc + (size_t)g_rowTok[r] * KD;
            else          aptr[p] = Asrc + (size_t)r * KD;
        } else aptr[p] = nullptr;
    }

    float acc[4][4][4];
#pragma unroll
    for (int mi = 0; mi < 4; mi++)
#pragma unroll
        for (int ni = 0; ni < 4; ni++)
#pragma unroll
            for (int q = 0; q < 4; q++) acc[mi][ni][q] = 0.f;

    int lane = tid & 31, wid = tid >> 5;
    int wm = (wid >> 2) * 64, wn = (wid & 3) * 32;
    int g = lane >> 2, tg = lane & 3;

    float4 ra[2], rb[2];

    auto LOADT = [&](int k0) {
#pragma unroll
        for (int p = 0; p < 2; p++) {
            if (aptr[p]) ra[p] = *(const float4*)(aptr[p] + k0 + ak);
            else         ra[p] = make_float4(0.f, 0.f, 0.f, 0.f);
            rb[p] = *(const float4*)(B + (size_t)(k0 + bk + 8 * p) * ND + bn);
        }
    };
    auto STORET = [&]() {
#pragma unroll
        for (int p = 0; p < 2; p++) {
            sA[am + 64 * p][ak + 0] = to_tf32(ra[p].x);
            sA[am + 64 * p][ak + 1] = to_tf32(ra[p].y);
            sA[am + 64 * p][ak + 2] = to_tf32(ra[p].z);
            sA[am + 64 * p][ak + 3] = to_tf32(ra[p].w);
            float4 tb;
            tb.x = to_tf32(rb[p].x); tb.y = to_tf32(rb[p].y);
            tb.z = to_tf32(rb[p].z); tb.w = to_tf32(rb[p].w);
            *(float4*)&sB[bk + 8 * p][bn] = tb;
        }
    };
    auto COMPUTE = [&]() {
#pragma unroll
        for (int ks = 0; ks < 16; ks += 8) {
            unsigned af[4][4], bf[4][2];
#pragma unroll
            for (int mi = 0; mi < 4; mi++) {
                int r_ = wm + mi * 16 + g;
                af[mi][0] = __float_as_uint(sA[r_][ks + tg]);
                af[mi][1] = __float_as_uint(sA[r_ + 8][ks + tg]);
                af[mi][2] = __float_as_uint(sA[r_][ks + tg + 4]);
                af[mi][3] = __float_as_uint(sA[r_ + 8][ks + tg + 4]);
            }
#pragma unroll
            for (int ni = 0; ni < 4; ni++) {
                int c_ = wn + ni * 8 + g;
                bf[ni][0] = __float_as_uint(sB[ks + tg][c_]);
                bf[ni][1] = __float_as_uint(sB[ks + tg + 4][c_]);
            }
#pragma unroll
            for (int mi = 0; mi < 4; mi++)
#pragma unroll
                for (int ni = 0; ni < 4; ni++) {
                    asm volatile(
                        "mma.sync.aligned.m16n8k8.row.col.f32.tf32.tf32.f32 "
                        "{%0,%1,%2,%3}, {%4,%5,%6,%7}, {%8,%9}, {%0,%1,%2,%3};\n"
                        : "+f"(acc[mi][ni][0]), "+f"(acc[mi][ni][1]),
                          "+f"(acc[mi][ni][2]), "+f"(acc[mi][ni][3])
                        : "r"(af[mi][0]), "r"(af[mi][1]), "r"(af[mi][2]), "r"(af[mi][3]),
                          "r"(bf[ni][0]), "r"(bf[ni][1]));
                }
        }
    };

    LOADT(0);
    STORET();
    __syncthreads();
    const int nkt = KD / 16;
    for (int kt = 1; kt < nkt; kt++) {
        LOADT(kt * 16);
        COMPUTE();
        __syncthreads();
        STORET();
        __syncthreads();
    }
    COMPUTE();

    // epilogue: bias (+ exact GELU), store fp32
#pragma unroll
    for (int mi = 0; mi < 4; mi++) {
        int mr = row0 + wm + mi * 16 + g;
#pragma unroll
        for (int ni = 0; ni < 4; ni++) {
            int nc = wn + ni * 8 + 2 * tg;
            float bb0 = bias[nc], bb1 = bias[nc + 1];
            float v0 = acc[mi][ni][0] + bb0, v1 = acc[mi][ni][1] + bb1;
            float v2 = acc[mi][ni][2] + bb0, v3 = acc[mi][ni][3] + bb1;
            if (DOGELU) {
                v0 = 0.5f * v0 * (1.f + erff(v0 * 0.70710678118654752f));
                v1 = 0.5f * v1 * (1.f + erff(v1 * 0.70710678118654752f));
                v2 = 0.5f * v2 * (1.f + erff(v2 * 0.70710678118654752f));
                v3 = 0.5f * v3 * (1.f + erff(v3 * 0.70710678118654752f));
            }
            *(float2*)(C + (size_t)mr * ND + nblk + nc)       = make_float2(v0, v1);
            *(float2*)(C + (size_t)(mr + 8) * ND + nblk + nc) = make_float2(v2, v3);
        }
    }
}

// ---------------- combine: out[t] = w0*Y[pos0] + w1*Y[pos1] ----------------
__global__ void k_combine(float* __restrict__ out) {
    int t = blockIdx.x;
    int p0 = g_pairPos[2 * t], p1 = g_pairPos[2 * t + 1];
    float w0 = g_w2[2 * t], w1 = g_w2[2 * t + 1];
    const float4* y0 = (const float4*)(g_Y + (size_t)p0 * HID);
    const float4* y1 = (const float4*)(g_Y + (size_t)p1 * HID);
    float4* o = (float4*)(out + (size_t)t * HID);
    int i = threadIdx.x;  // 256 threads * float4 = 1024
    float4 a = y0[i], b = y1[i], r;
    r.x = w0 * a.x + w1 * b.x;
    r.y = w0 * a.y + w1 * b.y;
    r.z = w0 * a.z + w1 * b.z;
    r.w = w0 * a.w + w1 * b.w;
    o[i] = r;
}

// ---------------- launch ----------------
extern "C" void kernel_launch(void* const* d_in, const int* in_sizes, int n_in,
                              void* d_out, int out_size) {
    const float* x  = (const float*)d_in[0];
    const float* Wr = (const float*)d_in[1];
    const float* W1 = (const float*)d_in[2];
    const float* b1 = (const float*)d_in[3];
    const float* W2 = (const float*)d_in[4];
    const float* b2 = (const float*)d_in[5];
    float* out = (float*)d_out;

    k_zero<<<1, 32>>>();
    k_router<<<NTOK / 8, 256>>>(x, Wr);
    k_offsets<<<1, 32>>>();
    k_place<<<(NTOK * 2) / 256, 256>>>();
    // GEMM1: (rows, HID) x (HID, FFN) -> GELU -> g_H ; A gathered from x via rowTok
    k_gemm<HID, FFN, true, true><<<dim3(FFN / 128, CAP / 128), 256>>>(x, W1, b1);
    // GEMM2: (rows, FFN) x (FFN, HID) -> g_Y ; A = g_H directly
    k_gemm<FFN, HID, false, false><<<dim3(HID / 128, CAP / 128), 256>>>(nullptr, W2, b2);
    k_combine<<<NTOK, 256>>>(out);
}

// round 3
// speedup vs baseline: 1.3974x; 1.3974x over previous
#include <cuda_runtime.h>
#include <math.h>
#include <stdint.h>

#define HID  1024
#define FFN  4096
#define NE   8
#define NTOK 4096
#define CAP  9216

#define BM 128
#define BN 256
#define BK 32
#define STAGES 3
#define APAD 36                       // floats per A smem row (conflict-free, 16B-aligned)
#define BPAD 264                      // floats per B smem row
#define ABYTES (BM * APAD * 4)        // 18432
#define BBYTES (BK * BPAD * 4)        // 33792
#define STGB   (ABYTES + BBYTES)      // 52224
#define SMEM_TOTAL (STAGES * STGB)    // 156672

// ---------------- scratch (device globals; no allocation allowed) ----------------
__device__ int   g_cnt[NE];
__device__ int   g_off[NE + 1];
__device__ int   g_end[NE];
__device__ int   g_cur[NE];
__device__ int   g_rowTok[CAP];
__device__ int   g_tok2[NTOK * 2];
__device__ float g_w2v[NTOK * 2];
__device__ int   g_pairPos[NTOK * 2];
__device__ float g_X[(size_t)CAP * HID];
__device__ float g_H[(size_t)CAP * FFN];
__device__ float g_Y[(size_t)CAP * HID];
__device__ float g_W1r[(size_t)NE * HID * FFN];   // RNA-rounded copy of W1
__device__ float g_W2r[(size_t)NE * FFN * HID];   // RNA-rounded copy of W2

// ---------------- helpers ----------------
__device__ __forceinline__ float to_tf32(float x) {
    unsigned u;
    asm("cvt.rna.tf32.f32 %0, %1;" : "=r"(u) : "f"(x));
    return __uint_as_float(u);
}
__device__ __forceinline__ uint32_t smem_u32(const void* p) {
    uint32_t a;
    asm("{ .reg .u64 t; cvta.to.shared.u64 t, %1; cvt.u32.u64 %0, t; }" : "=r"(a) : "l"(p));
    return a;
}
__device__ __forceinline__ void cpa16(uint32_t s, const void* g) {
    asm volatile("cp.async.cg.shared.global [%0], [%1], 16;\n" :: "r"(s), "l"(g));
}

// ---------------- routing ----------------
__global__ void k_zero() {
    if (threadIdx.x < NE) g_cnt[threadIdx.x] = 0;
}

__global__ void k_router(const float* __restrict__ x, const float* __restrict__ Wr) {
    int warp = threadIdx.x >> 5, lane = threadIdx.x & 31;
    int t = blockIdx.x * 8 + warp;
    const float* xr = x + (size_t)t * HID;
    float acc[NE];
#pragma unroll
    for (int e = 0; e < NE; e++) acc[e] = 0.f;
    for (int i = lane; i < HID; i += 32) {
        float xv = xr[i];
        const float4* w = (const float4*)(Wr + (size_t)i * NE);
        float4 w0 = w[0], w1 = w[1];
        acc[0] += xv * w0.x; acc[1] += xv * w0.y; acc[2] += xv * w0.z; acc[3] += xv * w0.w;
        acc[4] += xv * w1.x; acc[5] += xv * w1.y; acc[6] += xv * w1.z; acc[7] += xv * w1.w;
    }
#pragma unroll
    for (int e = 0; e < NE; e++)
#pragma unroll
        for (int s = 16; s > 0; s >>= 1) acc[e] += __shfl_xor_sync(0xffffffffu, acc[e], s);
    if (lane == 0) {
        int i0 = 0; float m0 = acc[0];
#pragma unroll
        for (int e = 1; e < NE; e++) if (acc[e] > m0) { m0 = acc[e]; i0 = e; }
        int i1 = -1; float m1 = -1e30f;
#pragma unroll
        for (int e = 0; e < NE; e++) if (e != i0 && acc[e] > m1) { m1 = acc[e]; i1 = e; }
        float w0 = 1.f / (1.f + expf(m1 - m0));
        g_tok2[2 * t] = i0; g_tok2[2 * t + 1] = i1;
        g_w2v[2 * t] = w0;  g_w2v[2 * t + 1] = 1.f - w0;
        atomicAdd(&g_cnt[i0], 1);
        atomicAdd(&g_cnt[i1], 1);
    }
}

__global__ void k_offsets() {
    if (threadIdx.x == 0) {
        int o = 0;
#pragma unroll
        for (int e = 0; e < NE; e++) {
            g_off[e] = o; g_end[e] = o + g_cnt[e]; g_cur[e] = o;
            o += (g_cnt[e] + 127) & ~127;
        }
        g_off[NE] = o;
    }
}

__global__ void k_place() {
    int p = blockIdx.x * blockDim.x + threadIdx.x;
    if (p < NTOK * 2) {
        int e = g_tok2[p];
        int r = atomicAdd(&g_cur[e], 1);
        g_rowTok[r] = p >> 1;
        g_pairPos[p] = r;
    }
}

// gather + RNA-round x into g_X; zero pad rows
__global__ void k_gather(const float* __restrict__ x) {
    int r = blockIdx.x;
    bool valid = false;
#pragma unroll
    for (int e = 0; e < NE; e++) valid |= (r >= g_off[e] && r < g_end[e]);
    float4* dst = (float4*)(g_X + (size_t)r * HID);
    if (valid) {
        const float4* src = (const float4*)(x + (size_t)g_rowTok[r] * HID);
        float4 v = src[threadIdx.x];
        v.x = to_tf32(v.x); v.y = to_tf32(v.y); v.z = to_tf32(v.z); v.w = to_tf32(v.w);
        dst[threadIdx.x] = v;
    } else {
        dst[threadIdx.x] = make_float4(0.f, 0.f, 0.f, 0.f);
    }
}

// elementwise RNA-round weights into rounded copies
__global__ void k_round(const float* __restrict__ src, int which, int n4) {
    float* dst = which ? g_W2r : g_W1r;
    const float4* s = (const float4*)src;
    float4* d = (float4*)dst;
    int stride = gridDim.x * blockDim.x;
    for (int i = blockIdx.x * blockDim.x + threadIdx.x; i < n4; i += stride) {
        float4 v = s[i];
        v.x = to_tf32(v.x); v.y = to_tf32(v.y); v.z = to_tf32(v.z); v.w = to_tf32(v.w);
        d[i] = v;
    }
}

// ---------------- pipelined TF32 mma.sync grouped GEMM ----------------
// CTA 128x256, 8 warps (2x4) of 64x64, BK=32, 3-stage cp.async.
template <int KD, int ND, bool DOGELU>
__global__ void __launch_bounds__(256, 1)
k_hgemm(const float* __restrict__ Bias) {
    extern __shared__ char smem[];

    int row0 = blockIdx.y * BM;
    if (row0 >= g_off[NE]) return;
    int e = 0;
    while (row0 >= g_off[e + 1]) e++;
    int nblk = blockIdx.x * BN;

    const float* A = DOGELU ? g_X : g_H;
    const float* B = (DOGELU ? g_W1r : g_W2r) + (size_t)e * KD * ND;
    float*       C = DOGELU ? g_H : g_Y;

    int tid = threadIdx.x;
    uint32_t sb = smem_u32(smem);

    // per-thread load slots
    const float* aS[4]; uint32_t aD[4];
    const float* bS[8]; uint32_t bD[8];
#pragma unroll
    for (int p = 0; p < 4; p++) {
        int i = tid + 256 * p;
        int r = i >> 3, j = i & 7;                  // 128 rows x 8 chunks of 16B
        aS[p] = A + (size_t)(row0 + r) * KD + j * 4;
        aD[p] = sb + r * (APAD * 4) + j * 16;
    }
#pragma unroll
    for (int p = 0; p < 8; p++) {
        int i = tid + 256 * p;
        int kr = i >> 6, j = i & 63;                // 32 k-rows x 64 chunks of 16B
        bS[p] = B + (size_t)kr * ND + nblk + j * 4;
        bD[p] = sb + ABYTES + kr * (BPAD * 4) + j * 16;
    }

    const int NKT = KD / BK;

    auto LOAD = [&](int kt) {
        uint32_t st = (kt % STAGES) * STGB;
        size_t ka = (size_t)kt * BK;
        size_t kb = (size_t)kt * BK * ND;
#pragma unroll
        for (int p = 0; p < 4; p++) cpa16(aD[p] + st, aS[p] + ka);
#pragma unroll
        for (int p = 0; p < 8; p++) cpa16(bD[p] + st, bS[p] + kb);
        asm volatile("cp.async.commit_group;" ::: "memory");
    };

    LOAD(0);
    LOAD(1);

    float acc[4][8][4];
#pragma unroll
    for (int mi = 0; mi < 4; mi++)
#pragma unroll
        for (int ni = 0; ni < 8; ni++)
#pragma unroll
            for (int q = 0; q < 4; q++) acc[mi][ni][q] = 0.f;

    int wid = tid >> 5, lane = tid & 31;
    int g = lane >> 2, tg = lane & 3;
    int wm = (wid >> 2) * 64, wn = (wid & 3) * 64;
    const float* sf = (const float*)smem;
    int abase = (wm + g) * APAD + tg;
    int bbase = tg * BPAD + wn + g;

    for (int kt = 0; kt < NKT; kt++) {
        asm volatile("cp.async.wait_group %0;" :: "n"(STAGES - 2));
        __syncthreads();
        if (kt + STAGES - 1 < NKT) LOAD(kt + STAGES - 1);
        else asm volatile("cp.async.commit_group;" ::: "memory");

        const float* sA = sf + (kt % STAGES) * (STGB / 4);
        const float* sB = sA + ABYTES / 4;
#pragma unroll
        for (int ks = 0; ks < BK; ks += 8) {
            unsigned af[4][4], bf[8][2];
#pragma unroll
            for (int mi = 0; mi < 4; mi++) {
                int ia = abase + mi * 16 * APAD + ks;
                af[mi][0] = __float_as_uint(sA[ia]);
                af[mi][1] = __float_as_uint(sA[ia + 8 * APAD]);
                af[mi][2] = __float_as_uint(sA[ia + 4]);
                af[mi][3] = __float_as_uint(sA[ia + 8 * APAD + 4]);
            }
#pragma unroll
            for (int ni = 0; ni < 8; ni++) {
                int ib = bbase + ks * BPAD + ni * 8;
                bf[ni][0] = __float_as_uint(sB[ib]);
                bf[ni][1] = __float_as_uint(sB[ib + 4 * BPAD]);
            }
#pragma unroll
            for (int mi = 0; mi < 4; mi++)
#pragma unroll
                for (int ni = 0; ni < 8; ni++) {
                    asm volatile(
                        "mma.sync.aligned.m16n8k8.row.col.f32.tf32.tf32.f32 "
                        "{%0,%1,%2,%3}, {%4,%5,%6,%7}, {%8,%9}, {%0,%1,%2,%3};\n"
                        : "+f"(acc[mi][ni][0]), "+f"(acc[mi][ni][1]),
                          "+f"(acc[mi][ni][2]), "+f"(acc[mi][ni][3])
                        : "r"(af[mi][0]), "r"(af[mi][1]), "r"(af[mi][2]), "r"(af[mi][3]),
                          "r"(bf[ni][0]), "r"(bf[ni][1]));
                }
        }
    }

    asm volatile("cp.async.wait_group 0;" ::: "memory");

    // epilogue
    const float* bias = Bias + (size_t)e * ND + nblk;
    float bv[16];
#pragma unroll
    for (int ni = 0; ni < 8; ni++) {
        bv[2 * ni]     = bias[wn + ni * 8 + 2 * tg];
        bv[2 * ni + 1] = bias[wn + ni * 8 + 2 * tg + 1];
    }
#pragma unroll
    for (int mi = 0; mi < 4; mi++) {
        int rr = row0 + wm + mi * 16 + g;
        float* c0 = C + (size_t)rr * ND + nblk;
        float* c1 = C + (size_t)(rr + 8) * ND + nblk;
#pragma unroll
        for (int ni = 0; ni < 8; ni++) {
            float v0 = acc[mi][ni][0] + bv[2 * ni];
            float v1 = acc[mi][ni][1] + bv[2 * ni + 1];
            float v2 = acc[mi][ni][2] + bv[2 * ni];
            float v3 = acc[mi][ni][3] + bv[2 * ni + 1];
            if (DOGELU) {
                v0 = to_tf32(0.5f * v0 * (1.f + erff(v0 * 0.70710678118654752f)));
                v1 = to_tf32(0.5f * v1 * (1.f + erff(v1 * 0.70710678118654752f)));
                v2 = to_tf32(0.5f * v2 * (1.f + erff(v2 * 0.70710678118654752f)));
                v3 = to_tf32(0.5f * v3 * (1.f + erff(v3 * 0.70710678118654752f)));
            }
            int nc = wn + ni * 8 + 2 * tg;
            *(float2*)(c0 + nc) = make_float2(v0, v1);
            *(float2*)(c1 + nc) = make_float2(v2, v3);
        }
    }
}

// ---------------- combine ----------------
__global__ void k_combine(float* __restrict__ out) {
    int t = blockIdx.x;
    int p0 = g_pairPos[2 * t], p1 = g_pairPos[2 * t + 1];
    float w0 = g_w2v[2 * t], w1 = g_w2v[2 * t + 1];
    const float4* y0 = (const float4*)(g_Y + (size_t)p0 * HID);
    const float4* y1 = (const float4*)(g_Y + (size_t)p1 * HID);
    float4* o = (float4*)(out + (size_t)t * HID);
    int i = threadIdx.x;
    float4 a = y0[i], b = y1[i], r;
    r.x = w0 * a.x + w1 * b.x;
    r.y = w0 * a.y + w1 * b.y;
    r.z = w0 * a.z + w1 * b.z;
    r.w = w0 * a.w + w1 * b.w;
    o[i] = r;
}

// ---------------- launch ----------------
extern "C" void kernel_launch(void* const* d_in, const int* in_sizes, int n_in,
                              void* d_out, int out_size) {
    const float* x  = (const float*)d_in[0];
    const float* Wr = (const float*)d_in[1];
    const float* W1 = (const float*)d_in[2];
    const float* b1 = (const float*)d_in[3];
    const float* W2 = (const float*)d_in[4];
    const float* b2 = (const float*)d_in[5];
    float* out = (float*)d_out;

    cudaFuncSetAttribute(k_hgemm<HID, FFN, true>,
                         cudaFuncAttributeMaxDynamicSharedMemorySize, SMEM_TOTAL);
    cudaFuncSetAttribute(k_hgemm<FFN, HID, false>,
                         cudaFuncAttributeMaxDynamicSharedMemorySize, SMEM_TOTAL);

    k_zero<<<1, 32>>>();
    k_router<<<NTOK / 8, 256>>>(x, Wr);
    k_offsets<<<1, 32>>>();
    k_place<<<(NTOK * 2) / 256, 256>>>();
    k_gather<<<CAP, 256>>>(x);
    k_round<<<4096, 256>>>(W1, 0, NE * HID * FFN / 4);
    k_round<<<4096, 256>>>(W2, 1, NE * FFN * HID / 4);

    k_hgemm<HID, FFN, true><<<dim3(FFN / BN, CAP / BM), 256, SMEM_TOTAL>>>(b1);
    k_hgemm<FFN, HID, false><<<dim3(HID / BN, CAP / BM), 256, SMEM_TOTAL>>>(b2);
    k_combine<<<NTOK, 256>>>(out);
}

// round 4
// speedup vs baseline: 1.4532x; 1.0399x over previous
#include <cuda_runtime.h>
#include <math.h>
#include <stdint.h>

#define HID  1024
#define FFN  4096
#define NE   8
#define NTOK 4096
#define CAP  9216

#define BM 128
#define BN 128
#define BK 32
#define STAGES 3
#define APAD 36                       // floats per A smem row (conflict-free)
#define BPAD 136                      // floats per B smem k-row (conflict-free)
#define ABYTES (BM * APAD * 4)        // 18432
#define BBYTES (BK * BPAD * 4)        // 17408
#define STGB   (ABYTES + BBYTES)      // 35840
#define SMEM_TOTAL (STAGES * STGB)    // 107520  -> 2 CTAs/SM

// ---------------- scratch (device globals; no allocation allowed) ----------------
__device__ int   g_cnt[NE];
__device__ int   g_off[NE + 1];
__device__ int   g_end[NE];
__device__ int   g_cur[NE];
__device__ int   g_rowTok[CAP];
__device__ int   g_tok2[NTOK * 2];
__device__ float g_w2v[NTOK * 2];
__device__ int   g_pairPos[NTOK * 2];
__device__ float g_X[(size_t)CAP * HID];
__device__ float g_H[(size_t)CAP * FFN];
__device__ float g_Y[(size_t)CAP * HID];
__device__ float g_W1r[(size_t)NE * HID * FFN];   // RNA-rounded copy of W1
__device__ float g_W2r[(size_t)NE * FFN * HID];   // RNA-rounded copy of W2

// ---------------- helpers ----------------
__device__ __forceinline__ float to_tf32(float x) {
    unsigned u;
    asm("cvt.rna.tf32.f32 %0, %1;" : "=r"(u) : "f"(x));
    return __uint_as_float(u);
}
__device__ __forceinline__ uint32_t smem_u32(const void* p) {
    uint32_t a;
    asm("{ .reg .u64 t; cvta.to.shared.u64 t, %1; cvt.u32.u64 %0, t; }" : "=r"(a) : "l"(p));
    return a;
}
__device__ __forceinline__ void cpa16(uint32_t s, const void* g) {
    asm volatile("cp.async.cg.shared.global [%0], [%1], 16;\n" :: "r"(s), "l"(g));
}

// ---------------- routing ----------------
__global__ void k_zero() {
    if (threadIdx.x < NE) g_cnt[threadIdx.x] = 0;
}

__global__ void k_router(const float* __restrict__ x, const float* __restrict__ Wr) {
    int warp = threadIdx.x >> 5, lane = threadIdx.x & 31;
    int t = blockIdx.x * 8 + warp;
    const float* xr = x + (size_t)t * HID;
    float acc[NE];
#pragma unroll
    for (int e = 0; e < NE; e++) acc[e] = 0.f;
    for (int i = lane; i < HID; i += 32) {
        float xv = xr[i];
        const float4* w = (const float4*)(Wr + (size_t)i * NE);
        float4 w0 = w[0], w1 = w[1];
        acc[0] += xv * w0.x; acc[1] += xv * w0.y; acc[2] += xv * w0.z; acc[3] += xv * w0.w;
        acc[4] += xv * w1.x; acc[5] += xv * w1.y; acc[6] += xv * w1.z; acc[7] += xv * w1.w;
    }
#pragma unroll
    for (int e = 0; e < NE; e++)
#pragma unroll
        for (int s = 16; s > 0; s >>= 1) acc[e] += __shfl_xor_sync(0xffffffffu, acc[e], s);
    if (lane == 0) {
        int i0 = 0; float m0 = acc[0];
#pragma unroll
        for (int e = 1; e < NE; e++) if (acc[e] > m0) { m0 = acc[e]; i0 = e; }
        int i1 = -1; float m1 = -1e30f;
#pragma unroll
        for (int e = 0; e < NE; e++) if (e != i0 && acc[e] > m1) { m1 = acc[e]; i1 = e; }
        float w0 = 1.f / (1.f + expf(m1 - m0));
        g_tok2[2 * t] = i0; g_tok2[2 * t + 1] = i1;
        g_w2v[2 * t] = w0;  g_w2v[2 * t + 1] = 1.f - w0;
        atomicAdd(&g_cnt[i0], 1);
        atomicAdd(&g_cnt[i1], 1);
    }
}

__global__ void k_offsets() {
    if (threadIdx.x == 0) {
        int o = 0;
#pragma unroll
        for (int e = 0; e < NE; e++) {
            g_off[e] = o; g_end[e] = o + g_cnt[e]; g_cur[e] = o;
            o += (g_cnt[e] + 127) & ~127;
        }
        g_off[NE] = o;
    }
}

__global__ void k_place() {
    int p = blockIdx.x * blockDim.x + threadIdx.x;
    if (p < NTOK * 2) {
        int e = g_tok2[p];
        int r = atomicAdd(&g_cur[e], 1);
        g_rowTok[r] = p >> 1;
        g_pairPos[p] = r;
    }
}

// gather + RNA-round x into g_X; zero pad rows
__global__ void k_gather(const float* __restrict__ x) {
    int r = blockIdx.x;
    bool valid = false;
#pragma unroll
    for (int e = 0; e < NE; e++) valid |= (r >= g_off[e] && r < g_end[e]);
    float4* dst = (float4*)(g_X + (size_t)r * HID);
    if (valid) {
        const float4* src = (const float4*)(x + (size_t)g_rowTok[r] * HID);
        float4 v = src[threadIdx.x];
        v.x = to_tf32(v.x); v.y = to_tf32(v.y); v.z = to_tf32(v.z); v.w = to_tf32(v.w);
        dst[threadIdx.x] = v;
    } else {
        dst[threadIdx.x] = make_float4(0.f, 0.f, 0.f, 0.f);
    }
}

// elementwise RNA-round weights into rounded copies
__global__ void k_round(const float* __restrict__ src, int which, int n4) {
    float* dst = which ? g_W2r : g_W1r;
    const float4* s = (const float4*)src;
    float4* d = (float4*)dst;
    int stride = gridDim.x * blockDim.x;
    for (int i = blockIdx.x * blockDim.x + threadIdx.x; i < n4; i += stride) {
        float4 v = s[i];
        v.x = to_tf32(v.x); v.y = to_tf32(v.y); v.z = to_tf32(v.z); v.w = to_tf32(v.w);
        d[i] = v;
    }
}

// ---------------- pipelined TF32 mma.sync grouped GEMM ----------------
// CTA 128x128, 4 warps (2x2) of 64x64, BK=32, 3-stage cp.async, 2 CTAs/SM.
template <int KD, int ND, bool DOGELU>
__global__ void __launch_bounds__(128, 2)
k_hgemm(const float* __restrict__ Bias) {
    extern __shared__ char smem[];

    int row0 = blockIdx.y * BM;
    if (row0 >= g_off[NE]) return;
    int e = 0;
    while (row0 >= g_off[e + 1]) e++;
    int nblk = blockIdx.x * BN;

    const float* A = DOGELU ? g_X : g_H;
    const float* B = (DOGELU ? g_W1r : g_W2r) + (size_t)e * KD * ND;
    float*       C = DOGELU ? g_H : g_Y;

    int tid = threadIdx.x;
    uint32_t sb = smem_u32(smem);

    // per-thread cp.async slots: A = 128 rows x 8 x 16B; B = 32 k-rows x 32 x 16B
    const float* aS[8]; uint32_t aD[8];
    const float* bS[8]; uint32_t bD[8];
#pragma unroll
    for (int p = 0; p < 8; p++) {
        int i = tid + 128 * p;
        int r = i >> 3, j = i & 7;
        aS[p] = A + (size_t)(row0 + r) * KD + j * 4;
        aD[p] = sb + r * (APAD * 4) + j * 16;
    }
#pragma unroll
    for (int p = 0; p < 8; p++) {
        int i = tid + 128 * p;
        int kr = i >> 5, j = i & 31;
        bS[p] = B + (size_t)kr * ND + nblk + j * 4;
        bD[p] = sb + ABYTES + kr * (BPAD * 4) + j * 16;
    }

    const int NKT = KD / BK;

    auto LOAD = [&](int kt) {
        uint32_t st = (kt % STAGES) * STGB;
        size_t ka = (size_t)kt * BK;
        size_t kb = (size_t)kt * BK * ND;
#pragma unroll
        for (int p = 0; p < 8; p++) cpa16(aD[p] + st, aS[p] + ka);
#pragma unroll
        for (int p = 0; p < 8; p++) cpa16(bD[p] + st, bS[p] + kb);
        asm volatile("cp.async.commit_group;" ::: "memory");
    };

    LOAD(0);
    LOAD(1);

    float acc[4][8][4];
#pragma unroll
    for (int mi = 0; mi < 4; mi++)
#pragma unroll
        for (int ni = 0; ni < 8; ni++)
#pragma unroll
            for (int q = 0; q < 4; q++) acc[mi][ni][q] = 0.f;

    int wid = tid >> 5, lane = tid & 31;
    int g = lane >> 2, tg = lane & 3;
    int wm = (wid >> 1) * 64, wn = (wid & 1) * 64;
    const float* sf = (const float*)smem;
    int abase = (wm + g) * APAD + tg;
    int bbase = tg * BPAD + wn + g;

    for (int kt = 0; kt < NKT; kt++) {
        asm volatile("cp.async.wait_group %0;" :: "n"(STAGES - 2));
        __syncthreads();
        if (kt + STAGES - 1 < NKT) LOAD(kt + STAGES - 1);
        else asm volatile("cp.async.commit_group;" ::: "memory");

        const float* sA = sf + (kt % STAGES) * (STGB / 4);
        const float* sB = sA + ABYTES / 4;
#pragma unroll
        for (int ks = 0; ks < BK; ks += 8) {
            unsigned af[4][4], bf[8][2];
#pragma unroll
            for (int mi = 0; mi < 4; mi++) {
                int ia = abase + mi * 16 * APAD + ks;
                af[mi][0] = __float_as_uint(sA[ia]);
                af[mi][1] = __float_as_uint(sA[ia + 8 * APAD]);
                af[mi][2] = __float_as_uint(sA[ia + 4]);
                af[mi][3] = __float_as_uint(sA[ia + 8 * APAD + 4]);
            }
#pragma unroll
            for (int ni = 0; ni < 8; ni++) {
                int ib = bbase + ks * BPAD + ni * 8;
                bf[ni][0] = __float_as_uint(sB[ib]);
                bf[ni][1] = __float_as_uint(sB[ib + 4 * BPAD]);
            }
#pragma unroll
            for (int mi = 0; mi < 4; mi++)
#pragma unroll
                for (int ni = 0; ni < 8; ni++) {
                    asm volatile(
                        "mma.sync.aligned.m16n8k8.row.col.f32.tf32.tf32.f32 "
                        "{%0,%1,%2,%3}, {%4,%5,%6,%7}, {%8,%9}, {%0,%1,%2,%3};\n"
                        : "+f"(acc[mi][ni][0]), "+f"(acc[mi][ni][1]),
                          "+f"(acc[mi][ni][2]), "+f"(acc[mi][ni][3])
                        : "r"(af[mi][0]), "r"(af[mi][1]), "r"(af[mi][2]), "r"(af[mi][3]),
                          "r"(bf[ni][0]), "r"(bf[ni][1]));
                }
        }
    }

    asm volatile("cp.async.wait_group 0;" ::: "memory");

    // epilogue
    const float* bias = Bias + (size_t)e * ND + nblk;
    float bv[16];
#pragma unroll
    for (int ni = 0; ni < 8; ni++) {
        bv[2 * ni]     = bias[wn + ni * 8 + 2 * tg];
        bv[2 * ni + 1] = bias[wn + ni * 8 + 2 * tg + 1];
    }
#pragma unroll
    for (int mi = 0; mi < 4; mi++) {
        int rr = row0 + wm + mi * 16 + g;
        float* c0 = C + (size_t)rr * ND + nblk;
        float* c1 = C + (size_t)(rr + 8) * ND + nblk;
#pragma unroll
        for (int ni = 0; ni < 8; ni++) {
            float v0 = acc[mi][ni][0] + bv[2 * ni];
            float v1 = acc[mi][ni][1] + bv[2 * ni + 1];
            float v2 = acc[mi][ni][2] + bv[2 * ni];
            float v3 = acc[mi][ni][3] + bv[2 * ni + 1];
            if (DOGELU) {
                v0 = to_tf32(0.5f * v0 * (1.f + erff(v0 * 0.70710678118654752f)));
                v1 = to_tf32(0.5f * v1 * (1.f + erff(v1 * 0.70710678118654752f)));
                v2 = to_tf32(0.5f * v2 * (1.f + erff(v2 * 0.70710678118654752f)));
                v3 = to_tf32(0.5f * v3 * (1.f + erff(v3 * 0.70710678118654752f)));
            }
            int nc = wn + ni * 8 + 2 * tg;
            *(float2*)(c0 + nc) = make_float2(v0, v1);
            *(float2*)(c1 + nc) = make_float2(v2, v3);
        }
    }
}

// ---------------- combine ----------------
__global__ void k_combine(float* __restrict__ out) {
    int t = blockIdx.x;
    int p0 = g_pairPos[2 * t], p1 = g_pairPos[2 * t + 1];
    float w0 = g_w2v[2 * t], w1 = g_w2v[2 * t + 1];
    const float4* y0 = (const float4*)(g_Y + (size_t)p0 * HID);
    const float4* y1 = (const float4*)(g_Y + (size_t)p1 * HID);
    float4* o = (float4*)(out + (size_t)t * HID);
    int i = threadIdx.x;
    float4 a = y0[i], b = y1[i], r;
    r.x = w0 * a.x + w1 * b.x;
    r.y = w0 * a.y + w1 * b.y;
    r.z = w0 * a.z + w1 * b.z;
    r.w = w0 * a.w + w1 * b.w;
    o[i] = r;
}

// ---------------- launch ----------------
extern "C" void kernel_launch(void* const* d_in, const int* in_sizes, int n_in,
                              void* d_out, int out_size) {
    const float* x  = (const float*)d_in[0];
    const float* Wr = (const float*)d_in[1];
    const float* W1 = (const float*)d_in[2];
    const float* b1 = (const float*)d_in[3];
    const float* W2 = (const float*)d_in[4];
    const float* b2 = (const float*)d_in[5];
    float* out = (float*)d_out;

    cudaFuncSetAttribute(k_hgemm<HID, FFN, true>,
                         cudaFuncAttributeMaxDynamicSharedMemorySize, SMEM_TOTAL);
    cudaFuncSetAttribute(k_hgemm<FFN, HID, false>,
                         cudaFuncAttributeMaxDynamicSharedMemorySize, SMEM_TOTAL);

    k_zero<<<1, 32>>>();
    k_router<<<NTOK / 8, 256>>>(x, Wr);
    k_offsets<<<1, 32>>>();
    k_place<<<(NTOK * 2) / 256, 256>>>();
    k_gather<<<CAP, 256>>>(x);
    k_round<<<4096, 256>>>(W1, 0, NE * HID * FFN / 4);
    k_round<<<4096, 256>>>(W2, 1, NE * FFN * HID / 4);

    k_hgemm<HID, FFN, true><<<dim3(FFN / BN, CAP / BM), 128, SMEM_TOTAL>>>(b1);
    k_hgemm<FFN, HID, false><<<dim3(HID / BN, CAP / BM), 128, SMEM_TOTAL>>>(b2);
    k_combine<<<NTOK, 256>>>(out);
}

// round 5
// speedup vs baseline: 2.9206x; 2.0098x over previous
#include <cuda_runtime.h>
#include <cuda_fp16.h>
#include <math.h>
#include <stdint.h>

#define HID  1024
#define FFN  4096
#define NE   8
#define NTOK 4096
#define CAP  9216

#define BM 128
#define BN 128
#define BK 32
#define STAGES 4
#define APAD 40                        // halves per A smem row (80 B, conflict-free LDSM)
#define BPAD 136                       // halves per B smem k-row (272 B, conflict-free LDSM)
#define ABYTES (BM * APAD * 2)         // 10240
#define BBYTES (BK * BPAD * 2)         // 8704
#define STGB   (ABYTES + BBYTES)       // 18944
#define SMEM_TOTAL (STAGES * STGB)     // 75776 -> 2 CTAs/SM

// ---------------- scratch (device globals) ----------------
__device__ int    g_cnt[NE];
__device__ int    g_off[NE + 1];
__device__ int    g_end[NE];
__device__ int    g_cur[NE];
__device__ int    g_rowTok[CAP];
__device__ int    g_tok2[NTOK * 2];
__device__ float  g_w2v[NTOK * 2];
__device__ int    g_pairPos[NTOK * 2];
__device__ __half g_Xh[(size_t)CAP * HID];
__device__ __half g_Hh[(size_t)CAP * FFN];
__device__ float  g_Y[(size_t)CAP * HID];
__device__ __half g_W1h[(size_t)NE * HID * FFN];
__device__ __half g_W2h[(size_t)NE * FFN * HID];

// ---------------- helpers ----------------
__device__ __forceinline__ uint32_t smem_u32(const void* p) {
    uint32_t a;
    asm("{ .reg .u64 t; cvta.to.shared.u64 t, %1; cvt.u32.u64 %0, t; }" : "=r"(a) : "l"(p));
    return a;
}
__device__ __forceinline__ void cpa16(uint32_t s, const void* g) {
    asm volatile("cp.async.cg.shared.global [%0], [%1], 16;\n" :: "r"(s), "l"(g));
}
__device__ __forceinline__ void ldsm4(unsigned* r, uint32_t a) {
    asm volatile("ldmatrix.sync.aligned.m8n8.x4.shared.b16 {%0,%1,%2,%3}, [%4];"
                 : "=r"(r[0]), "=r"(r[1]), "=r"(r[2]), "=r"(r[3]) : "r"(a));
}
__device__ __forceinline__ void ldsm4t(unsigned* r, uint32_t a) {
    asm volatile("ldmatrix.sync.aligned.m8n8.x4.trans.shared.b16 {%0,%1,%2,%3}, [%4];"
                 : "=r"(r[0]), "=r"(r[1]), "=r"(r[2]), "=r"(r[3]) : "r"(a));
}

// ---------------- routing ----------------
__global__ void k_zero() {
    if (threadIdx.x < NE) g_cnt[threadIdx.x] = 0;
}

__global__ void k_router(const float* __restrict__ x, const float* __restrict__ Wr) {
    int warp = threadIdx.x >> 5, lane = threadIdx.x & 31;
    int t = blockIdx.x * 8 + warp;
    const float* xr = x + (size_t)t * HID;
    float acc[NE];
#pragma unroll
    for (int e = 0; e < NE; e++) acc[e] = 0.f;
    for (int i = lane; i < HID; i += 32) {
        float xv = xr[i];
        const float4* w = (const float4*)(Wr + (size_t)i * NE);
        float4 w0 = w[0], w1 = w[1];
        acc[0] += xv * w0.x; acc[1] += xv * w0.y; acc[2] += xv * w0.z; acc[3] += xv * w0.w;
        acc[4] += xv * w1.x; acc[5] += xv * w1.y; acc[6] += xv * w1.z; acc[7] += xv * w1.w;
    }
#pragma unroll
    for (int e = 0; e < NE; e++)
#pragma unroll
        for (int s = 16; s > 0; s >>= 1) acc[e] += __shfl_xor_sync(0xffffffffu, acc[e], s);
    if (lane == 0) {
        int i0 = 0; float m0 = acc[0];
#pragma unroll
        for (int e = 1; e < NE; e++) if (acc[e] > m0) { m0 = acc[e]; i0 = e; }
        int i1 = -1; float m1 = -1e30f;
#pragma unroll
        for (int e = 0; e < NE; e++) if (e != i0 && acc[e] > m1) { m1 = acc[e]; i1 = e; }
        float w0 = 1.f / (1.f + expf(m1 - m0));
        g_tok2[2 * t] = i0; g_tok2[2 * t + 1] = i1;
        g_w2v[2 * t] = w0;  g_w2v[2 * t + 1] = 1.f - w0;
        atomicAdd(&g_cnt[i0], 1);
        atomicAdd(&g_cnt[i1], 1);
    }
}

__global__ void k_offsets() {
    if (threadIdx.x == 0) {
        int o = 0;
#pragma unroll
        for (int e = 0; e < NE; e++) {
            g_off[e] = o; g_end[e] = o + g_cnt[e]; g_cur[e] = o;
            o += (g_cnt[e] + 127) & ~127;
        }
        g_off[NE] = o;
    }
}

__global__ void k_place() {
    int p = blockIdx.x * blockDim.x + threadIdx.x;
    if (p < NTOK * 2) {
        int e = g_tok2[p];
        int r = atomicAdd(&g_cur[e], 1);
        g_rowTok[r] = p >> 1;
        g_pairPos[p] = r;
    }
}

// gather + fp16-convert x into g_Xh; zero pad rows
__global__ void k_gather(const float* __restrict__ x) {
    int r = blockIdx.x;
    bool valid = false;
#pragma unroll
    for (int e = 0; e < NE; e++) valid |= (r >= g_off[e] && r < g_end[e]);
    __half2* dst = (__half2*)(g_Xh + (size_t)r * HID);
    int i = threadIdx.x;  // 256 threads * 4 floats
    if (valid) {
        const float4* src = (const float4*)(x + (size_t)g_rowTok[r] * HID);
        float4 v = src[i];
        dst[2 * i]     = __floats2half2_rn(v.x, v.y);
        dst[2 * i + 1] = __floats2half2_rn(v.z, v.w);
    } else {
        dst[2 * i]     = __floats2half2_rn(0.f, 0.f);
        dst[2 * i + 1] = __floats2half2_rn(0.f, 0.f);
    }
}

// convert weights fp32 -> fp16 copies
__global__ void k_half(const float* __restrict__ src, int which, int n4) {
    __half2* d = which ? (__half2*)g_W2h : (__half2*)g_W1h;
    const float4* s = (const float4*)src;
    int stride = gridDim.x * blockDim.x;
    for (int i = blockIdx.x * blockDim.x + threadIdx.x; i < n4; i += stride) {
        float4 v = s[i];
        d[2 * i]     = __floats2half2_rn(v.x, v.y);
        d[2 * i + 1] = __floats2half2_rn(v.z, v.w);
    }
}

// ---------------- pipelined FP16 mma.sync grouped GEMM ----------------
// CTA 128x128, 4 warps (2x2) of 64x64, BK=32, 4-stage cp.async, 2 CTAs/SM.
template <int KD, int ND, bool DOGELU>
__global__ void __launch_bounds__(128, 2)
k_hgemm(const float* __restrict__ Bias) {
    extern __shared__ char smem[];

    int row0 = blockIdx.y * BM;
    if (row0 >= g_off[NE]) return;
    int e = 0;
    while (row0 >= g_off[e + 1]) e++;
    int nblk = blockIdx.x * BN;

    const __half* A = DOGELU ? g_Xh : g_Hh;
    const __half* B = (DOGELU ? g_W1h : g_W2h) + (size_t)e * KD * ND;

    int tid = threadIdx.x;
    uint32_t sb = smem_u32(smem);

    // cp.async slots: A = 128 rows x 4 chunks(16B=8 halves); B = 32 k-rows x 16 chunks
    const __half* aS[4]; uint32_t aD[4];
    const __half* bS[4]; uint32_t bD[4];
#pragma unroll
    for (int p = 0; p < 4; p++) {
        int i = tid + 128 * p;
        int r = i >> 2, j = i & 3;
        aS[p] = A + (size_t)(row0 + r) * KD + j * 8;
        aD[p] = sb + r * (APAD * 2) + j * 16;
    }
#pragma unroll
    for (int p = 0; p < 4; p++) {
        int i = tid + 128 * p;
        int kr = i >> 4, j = i & 15;
        bS[p] = B + (size_t)kr * ND + nblk + j * 8;
        bD[p] = sb + ABYTES + kr * (BPAD * 2) + j * 16;
    }

    const int NKT = KD / BK;

    auto LOAD = [&](int kt) {
        uint32_t st = (kt % STAGES) * STGB;
        size_t ka = (size_t)kt * BK;
        size_t kb = (size_t)kt * BK * ND;
#pragma unroll
        for (int p = 0; p < 4; p++) cpa16(aD[p] + st, aS[p] + ka);
#pragma unroll
        for (int p = 0; p < 4; p++) cpa16(bD[p] + st, bS[p] + kb);
        asm volatile("cp.async.commit_group;" ::: "memory");
    };

    LOAD(0); LOAD(1); LOAD(2);

    float acc[4][8][4];
#pragma unroll
    for (int mi = 0; mi < 4; mi++)
#pragma unroll
        for (int ni = 0; ni < 8; ni++)
#pragma unroll
            for (int q = 0; q < 4; q++) acc[mi][ni][q] = 0.f;

    int wid = tid >> 5, lane = tid & 31;
    int g = lane >> 2, tg = lane & 3;
    int wm = (wid >> 1) * 64, wn = (wid & 1) * 64;
    int lane8 = lane & 7, laneb = (lane >> 3) & 1, laneh = lane >> 4;

    // ldmatrix base addresses (stage offset added in loop)
    uint32_t aAddr0 = sb + ((wm + lane8 + laneb * 8) * APAD + laneh * 8) * 2;
    uint32_t bAddr0 = sb + ABYTES + ((lane8 + laneb * 8) * BPAD + wn + laneh * 8) * 2;

    for (int kt = 0; kt < NKT; kt++) {
        asm volatile("cp.async.wait_group %0;" :: "n"(STAGES - 2));
        __syncthreads();
        if (kt + STAGES - 1 < NKT) LOAD(kt + STAGES - 1);
        else asm volatile("cp.async.commit_group;" ::: "memory");

        uint32_t st = (kt % STAGES) * STGB;
#pragma unroll
        for (int ks = 0; ks < BK; ks += 16) {
            unsigned af[4][4], bf[8][2];
#pragma unroll
            for (int mi = 0; mi < 4; mi++)
                ldsm4(af[mi], aAddr0 + st + (mi * 16 * APAD + ks) * 2);
#pragma unroll
            for (int np = 0; np < 4; np++) {
                unsigned r[4];
                ldsm4t(r, bAddr0 + st + (ks * BPAD + np * 16) * 2);
                bf[2 * np][0] = r[0]; bf[2 * np][1] = r[1];
                bf[2 * np + 1][0] = r[2]; bf[2 * np + 1][1] = r[3];
            }
#pragma unroll
            for (int mi = 0; mi < 4; mi++)
#pragma unroll
                for (int ni = 0; ni < 8; ni++) {
                    asm volatile(
                        "mma.sync.aligned.m16n8k16.row.col.f32.f16.f16.f32 "
                        "{%0,%1,%2,%3}, {%4,%5,%6,%7}, {%8,%9}, {%0,%1,%2,%3};\n"
                        : "+f"(acc[mi][ni][0]), "+f"(acc[mi][ni][1]),
                          "+f"(acc[mi][ni][2]), "+f"(acc[mi][ni][3])
                        : "r"(af[mi][0]), "r"(af[mi][1]), "r"(af[mi][2]), "r"(af[mi][3]),
                          "r"(bf[ni][0]), "r"(bf[ni][1]));
                }
        }
    }

    asm volatile("cp.async.wait_group 0;" ::: "memory");

    // epilogue
    const float* bias = Bias + (size_t)e * ND + nblk;
    float bv[16];
#pragma unroll
    for (int ni = 0; ni < 8; ni++) {
        bv[2 * ni]     = bias[wn + ni * 8 + 2 * tg];
        bv[2 * ni + 1] = bias[wn + ni * 8 + 2 * tg + 1];
    }
#pragma unroll
    for (int mi = 0; mi < 4; mi++) {
        int rr = row0 + wm + mi * 16 + g;
#pragma unroll
        for (int ni = 0; ni < 8; ni++) {
            float v0 = acc[mi][ni][0] + bv[2 * ni];
            float v1 = acc[mi][ni][1] + bv[2 * ni + 1];
            float v2 = acc[mi][ni][2] + bv[2 * ni];
            float v3 = acc[mi][ni][3] + bv[2 * ni + 1];
            int nc = wn + ni * 8 + 2 * tg;
            if (DOGELU) {
                v0 = 0.5f * v0 * (1.f + erff(v0 * 0.70710678118654752f));
                v1 = 0.5f * v1 * (1.f + erff(v1 * 0.70710678118654752f));
                v2 = 0.5f * v2 * (1.f + erff(v2 * 0.70710678118654752f));
                v3 = 0.5f * v3 * (1.f + erff(v3 * 0.70710678118654752f));
                __half2* h0 = (__half2*)(g_Hh + (size_t)rr * ND + nblk + nc);
                __half2* h1 = (__half2*)(g_Hh + (size_t)(rr + 8) * ND + nblk + nc);
                *h0 = __floats2half2_rn(v0, v1);
                *h1 = __floats2half2_rn(v2, v3);
            } else {
                float* c0 = g_Y + (size_t)rr * ND + nblk;
                float* c1 = g_Y + (size_t)(rr + 8) * ND + nblk;
                *(float2*)(c0 + nc) = make_float2(v0, v1);
                *(float2*)(c1 + nc) = make_float2(v2, v3);
            }
        }
    }
}

// ---------------- combine ----------------
__global__ void k_combine(float* __restrict__ out) {
    int t = blockIdx.x;
    int p0 = g_pairPos[2 * t], p1 = g_pairPos[2 * t + 1];
    float w0 = g_w2v[2 * t], w1 = g_w2v[2 * t + 1];
    const float4* y0 = (const float4*)(g_Y + (size_t)p0 * HID);
    const float4* y1 = (const float4*)(g_Y + (size_t)p1 * HID);
    float4* o = (float4*)(out + (size_t)t * HID);
    int i = threadIdx.x;
    float4 a = y0[i], b = y1[i], r;
    r.x = w0 * a.x + w1 * b.x;
    r.y = w0 * a.y + w1 * b.y;
    r.z = w0 * a.z + w1 * b.z;
    r.w = w0 * a.w + w1 * b.w;
    o[i] = r;
}

// ---------------- launch ----------------
extern "C" void kernel_launch(void* const* d_in, const int* in_sizes, int n_in,
                              void* d_out, int out_size) {
    const float* x  = (const float*)d_in[0];
    const float* Wr = (const float*)d_in[1];
    const float* W1 = (const float*)d_in[2];
    const float* b1 = (const float*)d_in[3];
    const float* W2 = (const float*)d_in[4];
    const float* b2 = (const float*)d_in[5];
    float* out = (float*)d_out;

    cudaFuncSetAttribute(k_hgemm<HID, FFN, true>,
                         cudaFuncAttributeMaxDynamicSharedMemorySize, SMEM_TOTAL);
    cudaFuncSetAttribute(k_hgemm<FFN, HID, false>,
                         cudaFuncAttributeMaxDynamicSharedMemorySize, SMEM_TOTAL);

    k_zero<<<1, 32>>>();
    k_router<<<NTOK / 8, 256>>>(x, Wr);
    k_offsets<<<1, 32>>>();
    k_place<<<(NTOK * 2) / 256, 256>>>();
    k_gather<<<CAP, 256>>>(x);
    k_half<<<4096, 256>>>(W1, 0, NE * HID * FFN / 4);
    k_half<<<4096, 256>>>(W2, 1, NE * FFN * HID / 4);

    k_hgemm<HID, FFN, true><<<dim3(FFN / BN, CAP / BM), 128, SMEM_TOTAL>>>(b1);
    k_hgemm<FFN, HID, false><<<dim3(HID / BN, CAP / BM), 128, SMEM_TOTAL>>>(b2);
    k_combine<<<NTOK, 256>>>(out);
}

// round 7
// speedup vs baseline: 2.9455x; 1.0085x over previous
#include <cuda_runtime.h>
#include <cuda_fp16.h>
#include <math.h>
#include <stdint.h>

#define HID  1024
#define FFN  4096
#define NE   8
#define NTOK 4096
#define CAP  9216

#define BM 128
#define BN 128
#define BK 32
#define STAGES 4
#define APAD 40                        // halves per A smem row (80 B, conflict-free LDSM)
#define BPAD 136                       // halves per B smem k-row (272 B, conflict-free LDSM)
#define ABYTES (BM * APAD * 2)         // 10240
#define BBYTES (BK * BPAD * 2)         // 8704
#define STGB   (ABYTES + BBYTES)       // 18944
#define SMEM_TOTAL (STAGES * STGB)     // 75776 -> 2 CTAs/SM

// ---------------- scratch (device globals) ----------------
__device__ int    g_cnt[NE];
__device__ int    g_off[NE + 1];
__device__ int    g_end[NE];
__device__ int    g_cur[NE];
__device__ int    g_rowTok[CAP];
__device__ int    g_tok2[NTOK * 2];
__device__ float  g_w2v[NTOK * 2];
__device__ int    g_pairPos[NTOK * 2];
__device__ __half g_Xh[(size_t)CAP * HID];
__device__ __half g_Hh[(size_t)CAP * FFN];
__device__ __half g_Yh[(size_t)CAP * HID];
__device__ __half g_W1h[(size_t)NE * HID * FFN];
__device__ __half g_W2h[(size_t)NE * FFN * HID];

// ---------------- helpers ----------------
__device__ __forceinline__ uint32_t smem_u32(const void* p) {
    uint32_t a;
    asm("{ .reg .u64 t; cvta.to.shared.u64 t, %1; cvt.u32.u64 %0, t; }" : "=r"(a) : "l"(p));
    return a;
}
__device__ __forceinline__ void cpa16(uint32_t s, const void* g) {
    asm volatile("cp.async.cg.shared.global [%0], [%1], 16;\n" :: "r"(s), "l"(g));
}
__device__ __forceinline__ void ldsm4(unsigned* r, uint32_t a) {
    asm volatile("ldmatrix.sync.aligned.m8n8.x4.shared.b16 {%0,%1,%2,%3}, [%4];"
                 : "=r"(r[0]), "=r"(r[1]), "=r"(r[2]), "=r"(r[3]) : "r"(a));
}
__device__ __forceinline__ void ldsm4t(unsigned* r, uint32_t a) {
    asm volatile("ldmatrix.sync.aligned.m8n8.x4.trans.shared.b16 {%0,%1,%2,%3}, [%4];"
                 : "=r"(r[0]), "=r"(r[1]), "=r"(r[2]), "=r"(r[3]) : "r"(a));
}

// ---------------- fused prep: zero counters + convert both weights to fp16 ----------------
__global__ void k_prep(const float* __restrict__ W1, const float* __restrict__ W2) {
    if (blockIdx.x == 0 && threadIdx.x < NE) g_cnt[threadIdx.x] = 0;
    const int n4 = NE * HID * FFN / 4;   // same element count for both slabs
    __half2* d1 = (__half2*)g_W1h;
    __half2* d2 = (__half2*)g_W2h;
    const float4* s1 = (const float4*)W1;
    const float4* s2 = (const float4*)W2;
    int stride = gridDim.x * blockDim.x;
    for (int i = blockIdx.x * blockDim.x + threadIdx.x; i < n4; i += stride) {
        float4 v = s1[i];
        d1[2 * i]     = __floats2half2_rn(v.x, v.y);
        d1[2 * i + 1] = __floats2half2_rn(v.z, v.w);
        float4 u = s2[i];
        d2[2 * i]     = __floats2half2_rn(u.x, u.y);
        d2[2 * i + 1] = __floats2half2_rn(u.z, u.w);
    }
}

// ---------------- routing ----------------
__global__ void k_router(const float* __restrict__ x, const float* __restrict__ Wr) {
    int warp = threadIdx.x >> 5, lane = threadIdx.x & 31;
    int t = blockIdx.x * 8 + warp;
    const float* xr = x + (size_t)t * HID;
    float acc[NE];
#pragma unroll
    for (int e = 0; e < NE; e++) acc[e] = 0.f;
    for (int i = lane; i < HID; i += 32) {
        float xv = xr[i];
        const float4* w = (const float4*)(Wr + (size_t)i * NE);
        float4 w0 = w[0], w1 = w[1];
        acc[0] += xv * w0.x; acc[1] += xv * w0.y; acc[2] += xv * w0.z; acc[3] += xv * w0.w;
        acc[4] += xv * w1.x; acc[5] += xv * w1.y; acc[6] += xv * w1.z; acc[7] += xv * w1.w;
    }
#pragma unroll
    for (int e = 0; e < NE; e++)
#pragma unroll
        for (int s = 16; s > 0; s >>= 1) acc[e] += __shfl_xor_sync(0xffffffffu, acc[e], s);
    if (lane == 0) {
        int i0 = 0; float m0 = acc[0];
#pragma unroll
        for (int e = 1; e < NE; e++) if (acc[e] > m0) { m0 = acc[e]; i0 = e; }
        int i1 = -1; float m1 = -1e30f;
#pragma unroll
        for (int e = 0; e < NE; e++) if (e != i0 && acc[e] > m1) { m1 = acc[e]; i1 = e; }
        float w0 = 1.f / (1.f + expf(m1 - m0));
        g_tok2[2 * t] = i0; g_tok2[2 * t + 1] = i1;
        g_w2v[2 * t] = w0;  g_w2v[2 * t + 1] = 1.f - w0;
        atomicAdd(&g_cnt[i0], 1);
        atomicAdd(&g_cnt[i1], 1);
    }
}

__global__ void k_offsets() {
    if (threadIdx.x == 0) {
        int o = 0;
#pragma unroll
        for (int e = 0; e < NE; e++) {
            g_off[e] = o; g_end[e] = o + g_cnt[e]; g_cur[e] = o;
            o += (g_cnt[e] + 127) & ~127;
        }
        g_off[NE] = o;
    }
}

__global__ void k_place() {
    int p = blockIdx.x * blockDim.x + threadIdx.x;
    if (p < NTOK * 2) {
        int e = g_tok2[p];
        int r = atomicAdd(&g_cur[e], 1);
        g_rowTok[r] = p >> 1;
        g_pairPos[p] = r;
    }
}

// gather + fp16-convert x into g_Xh; zero pad rows
__global__ void k_gather(const float* __restrict__ x) {
    int r = blockIdx.x;
    bool valid = false;
#pragma unroll
    for (int e = 0; e < NE; e++) valid |= (r >= g_off[e] && r < g_end[e]);
    __half2* dst = (__half2*)(g_Xh + (size_t)r * HID);
    int i = threadIdx.x;  // 256 threads * 4 floats
    if (valid) {
        const float4* src = (const float4*)(x + (size_t)g_rowTok[r] * HID);
        float4 v = src[i];
        dst[2 * i]     = __floats2half2_rn(v.x, v.y);
        dst[2 * i + 1] = __floats2half2_rn(v.z, v.w);
    } else {
        dst[2 * i]     = __floats2half2_rn(0.f, 0.f);
        dst[2 * i + 1] = __floats2half2_rn(0.f, 0.f);
    }
}

// ---------------- pipelined FP16 mma.sync grouped GEMM ----------------
// CTA 128x128, 4 warps (2x2) of 64x64, BK=32, 4-stage cp.async, 2 CTAs/SM.
template <int KD, int ND, bool DOGELU>
__global__ void __launch_bounds__(128, 2)
k_hgemm(const float* __restrict__ Bias) {
    extern __shared__ char smem[];

    int row0 = blockIdx.y * BM;
    if (row0 >= g_off[NE]) return;
    int e = 0;
    while (row0 >= g_off[e + 1]) e++;
    int nblk = blockIdx.x * BN;

    const __half* A = DOGELU ? g_Xh : g_Hh;
    const __half* B = (DOGELU ? g_W1h : g_W2h) + (size_t)e * KD * ND;

    int tid = threadIdx.x;
    uint32_t sb = smem_u32(smem);

    // cp.async slots: A = 128 rows x 4 chunks(16B=8 halves); B = 32 k-rows x 16 chunks
    const __half* aS[4]; uint32_t aD[4];
    const __half* bS[4]; uint32_t bD[4];
#pragma unroll
    for (int p = 0; p < 4; p++) {
        int i = tid + 128 * p;
        int r = i >> 2, j = i & 3;
        aS[p] = A + (size_t)(row0 + r) * KD + j * 8;
        aD[p] = sb + r * (APAD * 2) + j * 16;
    }
#pragma unroll
    for (int p = 0; p < 4; p++) {
        int i = tid + 128 * p;
        int kr = i >> 4, j = i & 15;
        bS[p] = B + (size_t)kr * ND + nblk + j * 8;
        bD[p] = sb + ABYTES + kr * (BPAD * 2) + j * 16;
    }

    const int NKT = KD / BK;

    auto LOAD = [&](int kt) {
        uint32_t st = (kt % STAGES) * STGB;
        size_t ka = (size_t)kt * BK;
        size_t kb = (size_t)kt * BK * ND;
#pragma unroll
        for (int p = 0; p < 4; p++) cpa16(aD[p] + st, aS[p] + ka);
#pragma unroll
        for (int p = 0; p < 4; p++) cpa16(bD[p] + st, bS[p] + kb);
        asm volatile("cp.async.commit_group;" ::: "memory");
    };

    LOAD(0); LOAD(1); LOAD(2);

    float acc[4][8][4];
#pragma unroll
    for (int mi = 0; mi < 4; mi++)
#pragma unroll
        for (int ni = 0; ni < 8; ni++)
#pragma unroll
            for (int q = 0; q < 4; q++) acc[mi][ni][q] = 0.f;

    int wid = tid >> 5, lane = tid & 31;
    int g = lane >> 2, tg = lane & 3;
    int wm = (wid >> 1) * 64, wn = (wid & 1) * 64;
    int lane8 = lane & 7, laneb = (lane >> 3) & 1, laneh = lane >> 4;

    // ldmatrix base addresses (stage offset added in loop)
    uint32_t aAddr0 = sb + ((wm + lane8 + laneb * 8) * APAD + laneh * 8) * 2;
    uint32_t bAddr0 = sb + ABYTES + ((lane8 + laneb * 8) * BPAD + wn + laneh * 8) * 2;

    for (int kt = 0; kt < NKT; kt++) {
        asm volatile("cp.async.wait_group %0;" :: "n"(STAGES - 2));
        __syncthreads();
        if (kt + STAGES - 1 < NKT) LOAD(kt + STAGES - 1);
        else asm volatile("cp.async.commit_group;" ::: "memory");

        uint32_t st = (kt % STAGES) * STGB;
#pragma unroll
        for (int ks = 0; ks < BK; ks += 16) {
            unsigned af[4][4], bf[8][2];
#pragma unroll
            for (int mi = 0; mi < 4; mi++)
                ldsm4(af[mi], aAddr0 + st + (mi * 16 * APAD + ks) * 2);
#pragma unroll
            for (int np = 0; np < 4; np++) {
                unsigned r[4];
                ldsm4t(r, bAddr0 + st + (ks * BPAD + np * 16) * 2);
                bf[2 * np][0] = r[0]; bf[2 * np][1] = r[1];
                bf[2 * np + 1][0] = r[2]; bf[2 * np + 1][1] = r[3];
            }
#pragma unroll
            for (int mi = 0; mi < 4; mi++)
#pragma unroll
                for (int ni = 0; ni < 8; ni++) {
                    asm volatile(
                        "mma.sync.aligned.m16n8k16.row.col.f32.f16.f16.f32 "
                        "{%0,%1,%2,%3}, {%4,%5,%6,%7}, {%8,%9}, {%0,%1,%2,%3};\n"
                        : "+f"(acc[mi][ni][0]), "+f"(acc[mi][ni][1]),
                          "+f"(acc[mi][ni][2]), "+f"(acc[mi][ni][3])
                        : "r"(af[mi][0]), "r"(af[mi][1]), "r"(af[mi][2]), "r"(af[mi][3]),
                          "r"(bf[ni][0]), "r"(bf[ni][1]));
                }
        }
    }

    asm volatile("cp.async.wait_group 0;" ::: "memory");

    // epilogue
    const float* bias = Bias + (size_t)e * ND + nblk;
    float bv[16];
#pragma unroll
    for (int ni = 0; ni < 8; ni++) {
        bv[2 * ni]     = bias[wn + ni * 8 + 2 * tg];
        bv[2 * ni + 1] = bias[wn + ni * 8 + 2 * tg + 1];
    }
#pragma unroll
    for (int mi = 0; mi < 4; mi++) {
        int rr = row0 + wm + mi * 16 + g;
#pragma unroll
        for (int ni = 0; ni < 8; ni++) {
            float v0 = acc[mi][ni][0] + bv[2 * ni];
            float v1 = acc[mi][ni][1] + bv[2 * ni + 1];
            float v2 = acc[mi][ni][2] + bv[2 * ni];
            float v3 = acc[mi][ni][3] + bv[2 * ni + 1];
            int nc = wn + ni * 8 + 2 * tg;
            if (DOGELU) {
                v0 = 0.5f * v0 * (1.f + erff(v0 * 0.70710678118654752f));
                v1 = 0.5f * v1 * (1.f + erff(v1 * 0.70710678118654752f));
                v2 = 0.5f * v2 * (1.f + erff(v2 * 0.70710678118654752f));
                v3 = 0.5f * v3 * (1.f + erff(v3 * 0.70710678118654752f));
                __half2* h0 = (__half2*)(g_Hh + (size_t)rr * ND + nblk + nc);
                __half2* h1 = (__half2*)(g_Hh + (size_t)(rr + 8) * ND + nblk + nc);
                *h0 = __floats2half2_rn(v0, v1);
                *h1 = __floats2half2_rn(v2, v3);
            } else {
                __half2* y0 = (__half2*)(g_Yh + (size_t)rr * ND + nblk + nc);
                __half2* y1 = (__half2*)(g_Yh + (size_t)(rr + 8) * ND + nblk + nc);
                *y0 = __floats2half2_rn(v0, v1);
                *y1 = __floats2half2_rn(v2, v3);
            }
        }
    }
}

// ---------------- combine: out[t] = w0*Y[pos0] + w1*Y[pos1]  (fp16 Y, fp32 out) ----------------
__global__ void k_combine(float* __restrict__ out) {
    int t = blockIdx.x;
    int p0 = g_pairPos[2 * t], p1 = g_pairPos[2 * t + 1];
    float w0 = g_w2v[2 * t], w1 = g_w2v[2 * t + 1];
    const uint4* y0 = (const uint4*)(g_Yh + (size_t)p0 * HID);
    const uint4* y1 = (const uint4*)(g_Yh + (size_t)p1 * HID);
    float4* o = (float4*)(out + (size_t)t * HID);
    int i = threadIdx.x;                 // 128 threads * 8 halves
    uint4 a = y0[i], b = y1[i];
    const __half2* ah = (const __half2*)&a;
    const __half2* bh = (const __half2*)&b;
    float4 r0, r1;
    float2 a0 = __half22float2(ah[0]), b0 = __half22float2(bh[0]);
    float2 a1 = __half22float2(ah[1]), b1 = __half22float2(bh[1]);
    float2 a2 = __half22float2(ah[2]), b2 = __half22float2(bh[2]);
    float2 a3 = __half22float2(ah[3]), b3 = __half22float2(bh[3]);
    r0.x = w0 * a0.x + w1 * b0.x;  r0.y = w0 * a0.y + w1 * b0.y;
    r0.z = w0 * a1.x + w1 * b1.x;  r0.w = w0 * a1.y + w1 * b1.y;
    r1.x = w0 * a2.x + w1 * b2.x;  r1.y = w0 * a2.y + w1 * b2.y;
    r1.z = w0 * a3.x + w1 * b3.x;  r1.w = w0 * a3.y + w1 * b3.y;
    o[2 * i]     = r0;
    o[2 * i + 1] = r1;
}

// ---------------- launch ----------------
extern "C" void kernel_launch(void* const* d_in, const int* in_sizes, int n_in,
                              void* d_out, int out_size) {
    const float* x  = (const float*)d_in[0];
    const float* Wr = (const float*)d_in[1];
    const float* W1 = (const float*)d_in[2];
    const float* b1 = (const float*)d_in[3];
    const float* W2 = (const float*)d_in[4];
    const float* b2 = (const float*)d_in[5];
    float* out = (float*)d_out;

    cudaFuncSetAttribute(k_hgemm<HID, FFN, true>,
                         cudaFuncAttributeMaxDynamicSharedMemorySize, SMEM_TOTAL);
    cudaFuncSetAttribute(k_hgemm<FFN, HID, false>,
                         cudaFuncAttributeMaxDynamicSharedMemorySize, SMEM_TOTAL);

    k_prep<<<2048, 256>>>(W1, W2);
    k_router<<<NTOK / 8, 256>>>(x, Wr);
    k_offsets<<<1, 32>>>();
    k_place<<<(NTOK * 2) / 256, 256>>>();
    k_gather<<<CAP, 256>>>(x);

    k_hgemm<HID, FFN, true><<<dim3(FFN / BN, CAP / BM), 128, SMEM_TOTAL>>>(b1);
    k_hgemm<FFN, HID, false><<<dim3(HID / BN, CAP / BM), 128, SMEM_TOTAL>>>(b2);
    k_combine<<<NTOK, 128>>>(out);
}